// round 3
// baseline (speedup 1.0000x reference)
#include <cuda_runtime.h>
#include <math.h>

#define S_LEN 4096
#define BATCH 8
#define DMODEL 256
#define QPB 256
#define NTHREADS 256
#define SORT_THREADS 1024

// scratch (static __device__ allowed; no dynamic alloc)
__device__ float4 g_kdat[BATCH][S_LEN];  // (h - hmax, r, h + hmax, r), r = B2 * size_sentineled
__device__ float4 g_qdat[BATCH][S_LEN];  // (h_raw, size_true, orig_idx_bits, 0)
__device__ float  g_hmax[BATCH];

__device__ __forceinline__ float ex2_fast(float x) {
    float r;
    asm("ex2.approx.ftz.f32 %0, %1;" : "=f"(r) : "f"(x));
    return r;
}

// ---------------- sort kernel: one CTA per batch, bitonic over 4096 ----------------
__global__ __launch_bounds__(SORT_THREADS)
void dwsa_sort(const float* __restrict__ x)
{
    __shared__ float sk[S_LEN];
    __shared__ int   si[S_LEN];
    __shared__ float redm[SORT_THREADS / 32];

    const int b   = blockIdx.x;
    const int tid = threadIdx.x;
    const float2* xb = (const float2*)(x + (size_t)b * S_LEN * 2);

    float hm = 0.0f;
    for (int t = tid; t < S_LEN; t += SORT_THREADS) {
        float2 kv = xb[t];                       // .x = size, .y = height
        sk[t] = (kv.y == 0.0f) ? 3.0e9f : kv.x;  // masked keys sort last + huge r
        si[t] = t;
        hm = fmaxf(hm, fabsf(kv.y));
    }
    #pragma unroll
    for (int o = 16; o; o >>= 1) hm = fmaxf(hm, __shfl_down_sync(0xffffffffu, hm, o));
    if ((tid & 31) == 0) redm[tid >> 5] = hm;
    __syncthreads();
    if (tid == 0) {
        float m = redm[0];
        for (int i = 1; i < SORT_THREADS / 32; i++) m = fmaxf(m, redm[i]);
        g_hmax[b] = m;
        redm[0] = m;
    }
    __syncthreads();
    const float hmax = redm[0];

    // bitonic sort ascending by sk, payload si
    for (int k = 2; k <= S_LEN; k <<= 1) {
        for (int jj = k >> 1; jj > 0; jj >>= 1) {
            for (int t = tid; t < S_LEN; t += SORT_THREADS) {
                int p = t ^ jj;
                if (p > t) {
                    bool up = ((t & k) == 0);
                    float a = sk[t], c = sk[p];
                    if ((a > c) == up) {
                        sk[t] = c; sk[p] = a;
                        int ia = si[t]; si[t] = si[p]; si[p] = ia;
                    }
                }
            }
            __syncthreads();
        }
    }

    const float B2 = 0.5f * 1.4426950408889634f;
    for (int t = tid; t < S_LEN; t += SORT_THREADS) {
        int o = si[t];
        float2 kv = xb[o];
        float r = B2 * sk[t];
        g_kdat[b][t] = make_float4(kv.y - hmax, r, kv.y + hmax, r);
        g_qdat[b][t] = make_float4(kv.y, kv.x, __int_as_float(o), 0.0f);
    }
}

// ---------------- main kernel: 3 fma + 1 mufu per key ----------------
__global__ __launch_bounds__(NTHREADS)
void dwsa_main(const float* __restrict__ Wq,
               const float* __restrict__ Wk,
               const float* __restrict__ Wv,
               float* __restrict__ out)
{
    extern __shared__ char smem[];
    float2* kp2 = (float2*)smem;                          // 2*S_LEN float2 pairs
    float*  sWv = (float*)(smem + S_LEN * 16);            // DMODEL
    float*  sW  = sWv + DMODEL;                           // QPB
    int*    sOr = (int*)(sW + QPB);                       // QPB
    float*  red = (float*)(sOr + QPB);                    // 8

    const int tid  = threadIdx.x;
    const int b    = blockIdx.y;
    const int qblk = blockIdx.x;

    // load sorted key table into smem
    float4* kp4 = (float4*)smem;
    const float4* gk = g_kdat[b];
    #pragma unroll 4
    for (int t = tid; t < S_LEN; t += NTHREADS) kp4[t] = gk[t];
    sWv[tid] = Wv[tid];

    // dot(Wq, Wk)
    float p = Wq[tid] * Wk[tid];
    #pragma unroll
    for (int o = 16; o; o >>= 1) p += __shfl_down_sync(0xffffffffu, p, o);
    if ((tid & 31) == 0) red[tid >> 5] = p;
    __syncthreads();

    const float dotqk = red[0] + red[1] + red[2] + red[3]
                      + red[4] + red[5] + red[6] + red[7];
    const float LOG2E = 1.4426950408889634f;
    const float cs = dotqk * (1.0f / 16.0f) * LOG2E;
    const float B2 = 0.5f * LOG2E;
    const float hmax = g_hmax[b];

    // this thread's query = sorted rank j
    const int j = qblk * QPB + tid;
    const float4 qd = g_qdat[b][j];
    const float hq   = qd.x;
    const float zq   = qd.y;
    const int   orig = __float_as_int(qd.z);
    const float aq   = cs * hq;

    // pick shifted-height variant: aq>=0 -> (h - hmax) at word 0; aq<0 -> (h + hmax) at word 2
    const int sel = (aq >= 0.0f) ? 0 : 1;
    const float2* kq = kp2 + sel;     // kq[2*t] = (h', r) for key t

    float slo0 = 0.f, slo1 = 0.f, slo2 = 0.f, slo3 = 0.f;
    float wlo0 = 0.f, wlo1 = 0.f, wlo2 = 0.f, wlo3 = 0.f;
    float shi0 = 0.f, shi1 = 0.f, shi2 = 0.f, shi3 = 0.f;
    float whi0 = 0.f, whi1 = 0.f, whi2 = 0.f, whi3 = 0.f;

    const int wbase = qblk * QPB + (tid & ~31);   // multiple of 32

    // ---- lower region: keys [0, wbase), sz_t <= zq for every lane: l = aq*h' + r
    #pragma unroll 1
    for (int t = 0; t < wbase; t += 8) {
        float2 p0 = kq[2 * (t + 0)];
        float2 p1 = kq[2 * (t + 1)];
        float2 p2 = kq[2 * (t + 2)];
        float2 p3 = kq[2 * (t + 3)];
        float2 p4 = kq[2 * (t + 4)];
        float2 p5 = kq[2 * (t + 5)];
        float2 p6 = kq[2 * (t + 6)];
        float2 p7 = kq[2 * (t + 7)];
        float e0 = ex2_fast(fmaf(aq, p0.x, p0.y));
        float e1 = ex2_fast(fmaf(aq, p1.x, p1.y));
        float e2 = ex2_fast(fmaf(aq, p2.x, p2.y));
        float e3 = ex2_fast(fmaf(aq, p3.x, p3.y));
        float e4 = ex2_fast(fmaf(aq, p4.x, p4.y));
        float e5 = ex2_fast(fmaf(aq, p5.x, p5.y));
        float e6 = ex2_fast(fmaf(aq, p6.x, p6.y));
        float e7 = ex2_fast(fmaf(aq, p7.x, p7.y));
        slo0 += e0; slo1 += e1; slo2 += e2; slo3 += e3;
        slo0 += e4; slo1 += e5; slo2 += e6; slo3 += e7;
        wlo0 = fmaf(e0, p0.x, wlo0); wlo1 = fmaf(e1, p1.x, wlo1);
        wlo2 = fmaf(e2, p2.x, wlo2); wlo3 = fmaf(e3, p3.x, wlo3);
        wlo0 = fmaf(e4, p4.x, wlo0); wlo1 = fmaf(e5, p5.x, wlo1);
        wlo2 = fmaf(e6, p6.x, wlo2); wlo3 = fmaf(e7, p7.x, wlo3);
    }

    // ---- boundary block: keys [wbase, wbase+32), mixed per lane (t <= j -> lower)
    #pragma unroll 1
    for (int t = wbase; t < wbase + 32; ++t) {
        float2 pk = kq[2 * t];
        bool low = (t <= j);
        float rr = low ? pk.y : -pk.y;
        float e = ex2_fast(fmaf(aq, pk.x, rr));
        if (low) { slo0 += e; wlo0 = fmaf(e, pk.x, wlo0); }
        else     { shi0 += e; whi0 = fmaf(e, pk.x, whi0); }
    }

    // ---- upper region: keys [wbase+32, S_LEN), sz_t >= zq: l = aq*h' - r
    #pragma unroll 1
    for (int t = wbase + 32; t < S_LEN; t += 8) {
        float2 p0 = kq[2 * (t + 0)];
        float2 p1 = kq[2 * (t + 1)];
        float2 p2 = kq[2 * (t + 2)];
        float2 p3 = kq[2 * (t + 3)];
        float2 p4 = kq[2 * (t + 4)];
        float2 p5 = kq[2 * (t + 5)];
        float2 p6 = kq[2 * (t + 6)];
        float2 p7 = kq[2 * (t + 7)];
        float e0 = ex2_fast(fmaf(aq, p0.x, -p0.y));
        float e1 = ex2_fast(fmaf(aq, p1.x, -p1.y));
        float e2 = ex2_fast(fmaf(aq, p2.x, -p2.y));
        float e3 = ex2_fast(fmaf(aq, p3.x, -p3.y));
        float e4 = ex2_fast(fmaf(aq, p4.x, -p4.y));
        float e5 = ex2_fast(fmaf(aq, p5.x, -p5.y));
        float e6 = ex2_fast(fmaf(aq, p6.x, -p6.y));
        float e7 = ex2_fast(fmaf(aq, p7.x, -p7.y));
        shi0 += e0; shi1 += e1; shi2 += e2; shi3 += e3;
        shi0 += e4; shi1 += e5; shi2 += e6; shi3 += e7;
        whi0 = fmaf(e0, p0.x, whi0); whi1 = fmaf(e1, p1.x, whi1);
        whi2 = fmaf(e2, p2.x, whi2); whi3 = fmaf(e3, p3.x, whi3);
        whi0 = fmaf(e4, p4.x, whi0); whi1 = fmaf(e5, p5.x, whi1);
        whi2 = fmaf(e6, p6.x, whi2); whi3 = fmaf(e7, p7.x, whi3);
    }

    // ---- recombine: true term scales are 2^(-B2*zq) for lower, 2^(+B2*zq) for upper
    const float slo = (slo0 + slo1) + (slo2 + slo3);
    const float wlo = (wlo0 + wlo1) + (wlo2 + wlo3);
    const float shi = (shi0 + shi1) + (shi2 + shi3);
    const float whi = (whi0 + whi1) + (whi2 + whi3);
    const float flo = ex2_fast(-B2 * zq);
    const float fhi = ex2_fast( B2 * zq);
    const float se = fmaf(slo, flo, shi * fhi);
    const float swp = fmaf(wlo, flo, whi * fhi);
    const float w = swp / se + ((aq >= 0.0f) ? hmax : -hmax);  // undo h' shift

    sW[tid]  = w;
    sOr[tid] = orig;
    __syncthreads();

    // ---- epilogue: scatter rows (each row 1KB contiguous, float4 coalesced)
    const float4* wv4 = (const float4*)sWv;
    float* outb = out + (size_t)b * S_LEN * DMODEL;
    #pragma unroll 4
    for (int i = tid; i < QPB * (DMODEL / 4); i += NTHREADS) {
        const int row = i >> 6;          // 64 float4 per row
        const int c4  = i & 63;
        const float wv = sW[row];
        float4 v = wv4[c4];
        v.x *= wv; v.y *= wv; v.z *= wv; v.w *= wv;
        ((float4*)(outb + (size_t)sOr[row] * DMODEL))[c4] = v;
    }
}

extern "C" void kernel_launch(void* const* d_in, const int* in_sizes, int n_in,
                              void* d_out, int out_size)
{
    const float* x  = (const float*)d_in[0];
    const float* Wq = (const float*)d_in[1];
    const float* Wk = (const float*)d_in[2];
    const float* Wv = (const float*)d_in[3];
    float* out = (float*)d_out;

    const int smem_bytes = S_LEN * 16 + DMODEL * 4 + QPB * 4 + QPB * 4 + 64;
    cudaFuncSetAttribute(dwsa_main, cudaFuncAttributeMaxDynamicSharedMemorySize, smem_bytes);

    dwsa_sort<<<BATCH, SORT_THREADS>>>(x);
    dim3 grid(S_LEN / QPB, BATCH);
    dwsa_main<<<grid, NTHREADS, smem_bytes>>>(Wq, Wk, Wv, out);
}

// round 4
// speedup vs baseline: 2.2861x; 2.2861x over previous
#include <cuda_runtime.h>
#include <math.h>

#define S_LEN    4096
#define BATCH    8
#define DMODEL   256
#define QPB      256
#define NTHREADS 512
#define NPAIRS   (S_LEN / 2)

typedef unsigned long long ull;

__device__ __forceinline__ float ex2_fast(float x) {
    float r;
    asm("ex2.approx.ftz.f32 %0, %1;" : "=f"(r) : "f"(x));
    return r;
}
__device__ __forceinline__ ull pk2(float a, float b) {
    ull r; asm("mov.b64 %0, {%1, %2};" : "=l"(r) : "f"(a), "f"(b)); return r;
}
__device__ __forceinline__ void upk2(ull v, float& a, float& b) {
    asm("mov.b64 {%0, %1}, %2;" : "=f"(a), "=f"(b) : "l"(v));
}
__device__ __forceinline__ ull fma2(ull a, ull b, ull c) {
    ull r; asm("fma.rn.f32x2 %0, %1, %2, %3;" : "=l"(r) : "l"(a), "l"(b), "l"(c)); return r;
}
__device__ __forceinline__ ull add2(ull a, ull b) {
    ull r; asm("add.rn.f32x2 %0, %1, %2;" : "=l"(r) : "l"(a), "l"(b)); return r;
}

// out[b,s,:] = (sw/se) * Wv[:]
//   l(s,t) = aq*h_t - B2*|sz_s - sz_t| + nm ;  aq = (Wq.Wk/16)*log2e*h_s ; nm = -|aq|*hmax
__global__ __launch_bounds__(NTHREADS)
void dwsa_kernel(const float* __restrict__ x,
                 const float* __restrict__ Wq,
                 const float* __restrict__ Wk,
                 const float* __restrict__ Wv,
                 float* __restrict__ out)
{
    __shared__ float4 kp[NPAIRS];          // {h0, h1, -sz0m, -sz1m} per key pair (32 KB)
    __shared__ float  sWv[DMODEL];
    __shared__ float  sW[QPB];
    __shared__ float  pSe[2][QPB];
    __shared__ float  pSw[2][QPB];
    __shared__ float  redD[16];
    __shared__ float  redM[16];

    const int tid  = threadIdx.x;
    const int b    = blockIdx.y;
    const int qblk = blockIdx.x;

    const float2* xb = (const float2*)(x + (size_t)b * S_LEN * 2);
    const float4* xb4 = (const float4*)xb;      // {sz0, h0, sz1, h1}

    // ---- load keys (packed-friendly layout), fold key mask into negated size sentinel
    float hm = 0.0f;
    #pragma unroll
    for (int pi = tid; pi < NPAIRS; pi += NTHREADS) {
        float4 v = xb4[pi];
        float nsz0 = (v.y == 0.0f) ? -3.0e9f : -v.x;
        float nsz1 = (v.w == 0.0f) ? -3.0e9f : -v.z;
        kp[pi] = make_float4(v.y, v.w, nsz0, nsz1);
        hm = fmaxf(hm, fmaxf(fabsf(v.y), fabsf(v.w)));
    }
    if (tid < DMODEL) sWv[tid] = Wv[tid];

    // ---- block reductions: dot(Wq,Wk) (first 256 threads contribute) and max|h|
    float p = (tid < DMODEL) ? Wq[tid] * Wk[tid] : 0.0f;
    #pragma unroll
    for (int o = 16; o; o >>= 1) {
        p  += __shfl_down_sync(0xffffffffu, p, o);
        hm  = fmaxf(hm, __shfl_down_sync(0xffffffffu, hm, o));
    }
    if ((tid & 31) == 0) { redD[tid >> 5] = p; redM[tid >> 5] = hm; }
    __syncthreads();

    float dotqk = 0.0f, hmax = 0.0f;
    #pragma unroll
    for (int i = 0; i < 16; i++) { dotqk += redD[i]; hmax = fmaxf(hmax, redM[i]); }

    const float LOG2E = 1.4426950408889634f;
    const float cs  = dotqk * (1.0f / 16.0f) * LOG2E;
    const float nB2 = -0.5f * LOG2E;

    // ---- query assignment: 2 threads per query, each scans half the keys
    const int qi   = tid & (QPB - 1);
    const int half = tid >> 8;
    const int q    = qblk * QPB + qi;
    const float2 myx = xb[q];
    const float hq = myx.y;
    const float zq = myx.x;
    const float aq = cs * hq;
    const float nm = -fabsf(aq) * hmax;

    const ull aq2  = pk2(aq, aq);
    const ull nm2  = pk2(nm, nm);
    const ull zq2  = pk2(zq, zq);
    const ull nB22 = pk2(nB2, nB2);
    const ull ABSM = 0x7fffffff7fffffffULL;

    ull s2a = 0, s2b = 0, w2a = 0, w2b = 0;   // packed {0.f,0.f}

    const int p0 = half * (NPAIRS / 2);
    const int p1 = p0 + (NPAIRS / 2);

    #pragma unroll 2
    for (int pi = p0; pi < p1; pi += 4) {
        float4 va = kp[pi + 0];
        float4 vb = kp[pi + 1];
        float4 vc = kp[pi + 2];
        float4 vd = kp[pi + 3];

        ull ha = pk2(va.x, va.y), na = pk2(va.z, va.w);
        ull hb = pk2(vb.x, vb.y), nb = pk2(vb.z, vb.w);
        ull hc = pk2(vc.x, vc.y), nc = pk2(vc.z, vc.w);
        ull hd = pk2(vd.x, vd.y), nd = pk2(vd.z, vd.w);

        ull la = fma2(nB22, add2(zq2, na) & ABSM, fma2(aq2, ha, nm2));
        ull lb = fma2(nB22, add2(zq2, nb) & ABSM, fma2(aq2, hb, nm2));
        ull lc = fma2(nB22, add2(zq2, nc) & ABSM, fma2(aq2, hc, nm2));
        ull ld = fma2(nB22, add2(zq2, nd) & ABSM, fma2(aq2, hd, nm2));

        float l0, l1; upk2(la, l0, l1);
        float l2, l3; upk2(lb, l2, l3);
        float l4, l5; upk2(lc, l4, l5);
        float l6, l7; upk2(ld, l6, l7);

        ull ea = pk2(ex2_fast(l0), ex2_fast(l1));
        ull eb = pk2(ex2_fast(l2), ex2_fast(l3));
        ull ec = pk2(ex2_fast(l4), ex2_fast(l5));
        ull ed = pk2(ex2_fast(l6), ex2_fast(l7));

        s2a = add2(s2a, ea);  s2b = add2(s2b, eb);
        s2a = add2(s2a, ec);  s2b = add2(s2b, ed);
        w2a = fma2(ea, ha, w2a);  w2b = fma2(eb, hb, w2b);
        w2a = fma2(ec, hc, w2a);  w2b = fma2(ed, hd, w2b);
    }

    float sa0, sa1, sb0, sb1, wa0, wa1, wb0, wb1;
    upk2(s2a, sa0, sa1); upk2(s2b, sb0, sb1);
    upk2(w2a, wa0, wa1); upk2(w2b, wb0, wb1);
    pSe[half][qi] = (sa0 + sa1) + (sb0 + sb1);
    pSw[half][qi] = (wa0 + wa1) + (wb0 + wb1);
    __syncthreads();

    if (tid < QPB) {
        const float se = pSe[0][tid] + pSe[1][tid];
        const float sw = pSw[0][tid] + pSw[1][tid];
        sW[tid] = sw / se;
    }
    __syncthreads();

    // ---- epilogue: out[row,:] = sW[row] * Wv[:], float4 coalesced
    float4* ob = (float4*)(out + ((size_t)b * S_LEN + (size_t)qblk * QPB) * DMODEL);
    const float4* wv4 = (const float4*)sWv;
    #pragma unroll 4
    for (int i = tid; i < QPB * (DMODEL / 4); i += NTHREADS) {
        const int row = i >> 6;            // 64 float4 per row
        const float wv = sW[row];
        float4 v = wv4[i & 63];
        v.x *= wv; v.y *= wv; v.z *= wv; v.w *= wv;
        ob[i] = v;
    }
}

extern "C" void kernel_launch(void* const* d_in, const int* in_sizes, int n_in,
                              void* d_out, int out_size)
{
    const float* x  = (const float*)d_in[0];
    const float* Wq = (const float*)d_in[1];
    const float* Wk = (const float*)d_in[2];
    const float* Wv = (const float*)d_in[3];
    float* out = (float*)d_out;

    dim3 grid(S_LEN / QPB, BATCH);   // (16, 8) = 128 CTAs, one wave
    dwsa_kernel<<<grid, NTHREADS>>>(x, Wq, Wk, Wv, out);
}

// round 5
// speedup vs baseline: 2.5829x; 1.1299x over previous
#include <cuda_runtime.h>
#include <math.h>

#define S_LEN    4096
#define BATCH    8
#define DMODEL   256
#define NTHREADS 1024
#define NPAIRS   (S_LEN / 2)
#define ITEMS_TOTAL (BATCH * (S_LEN / 32))   // 1024 items of 32 queries
#define GRID     148

typedef unsigned long long ull;

__device__ __forceinline__ float ex2_fast(float x) {
    float r;
    asm("ex2.approx.ftz.f32 %0, %1;" : "=f"(r) : "f"(x));
    return r;
}
__device__ __forceinline__ ull pk2(float a, float b) {
    ull r; asm("mov.b64 %0, {%1, %2};" : "=l"(r) : "f"(a), "f"(b)); return r;
}
__device__ __forceinline__ void upk2(ull v, float& a, float& b) {
    asm("mov.b64 {%0, %1}, %2;" : "=f"(a), "=f"(b) : "l"(v));
}
__device__ __forceinline__ ull fma2(ull a, ull b, ull c) {
    ull r; asm("fma.rn.f32x2 %0, %1, %2, %3;" : "=l"(r) : "l"(a), "l"(b), "l"(c)); return r;
}
__device__ __forceinline__ ull add2(ull a, ull b) {
    ull r; asm("add.rn.f32x2 %0, %1, %2;" : "=l"(r) : "l"(a), "l"(b)); return r;
}

// out[b,s,:] = (sw/se)*Wv[:],  l(s,t) = aq*h_t - B2*|sz_s - sz_t| + nm
__global__ __launch_bounds__(NTHREADS, 1)
void dwsa_kernel(const float* __restrict__ x,
                 const float* __restrict__ Wq,
                 const float* __restrict__ Wk,
                 const float* __restrict__ Wv,
                 float* __restrict__ out)
{
    __shared__ float4 kp[NPAIRS];      // {h0, h1, -sz0m, -sz1m} per key pair (32 KB)
    __shared__ float  sWv[DMODEL];
    __shared__ float  redD[32];
    __shared__ float  redM[32];

    const int tid  = threadIdx.x;
    const int wid  = tid >> 5;
    const int lane = tid & 31;

    // ---- dot(Wq,Wk) once per CTA
    float p = (tid < DMODEL) ? Wq[tid] * Wk[tid] : 0.0f;
    #pragma unroll
    for (int o = 16; o; o >>= 1) p += __shfl_xor_sync(0xffffffffu, p, o);
    if (lane == 0) redD[wid] = p;
    if (tid < DMODEL) sWv[tid] = Wv[tid];
    __syncthreads();
    float dotqk = 0.0f;
    #pragma unroll
    for (int i = 0; i < 32; i++) dotqk += redD[i];

    const float LOG2E = 1.4426950408889634f;
    const float cs  = dotqk * (1.0f / 16.0f) * LOG2E;
    const float nB2 = -0.5f * LOG2E;
    const ull  nB22 = pk2(nB2, nB2);
    const ull  ABSM = 0x7fffffff7fffffffULL;

    // ---- static balanced item range for this CTA
    const int start = (blockIdx.x * ITEMS_TOTAL) / GRID;
    const int end   = ((blockIdx.x + 1) * ITEMS_TOTAL) / GRID;

    int   cur_b = -1;
    float hmax  = 0.0f;

    for (int it = start; it < end; ++it) {
        const int b     = it >> 7;        // 128 items per batch
        const int chunk = it & 127;
        const float4* xb4 = (const float4*)(x + (size_t)b * S_LEN * 2); // {sz0,h0,sz1,h1}

        if (b != cur_b) {
            __syncthreads();              // all warps done reading old keys
            float hm = 0.0f;
            #pragma unroll
            for (int pi = tid; pi < NPAIRS; pi += NTHREADS) {
                float4 v = xb4[pi];
                float n0 = (v.y == 0.0f) ? -3.0e9f : -v.x;
                float n1 = (v.w == 0.0f) ? -3.0e9f : -v.z;
                kp[pi] = make_float4(v.y, v.w, n0, n1);
                hm = fmaxf(hm, fmaxf(fabsf(v.y), fabsf(v.w)));
            }
            #pragma unroll
            for (int o = 16; o; o >>= 1) hm = fmaxf(hm, __shfl_xor_sync(0xffffffffu, hm, o));
            if (lane == 0) redM[wid] = hm;
            __syncthreads();
            hm = redM[0];
            #pragma unroll
            for (int i = 1; i < 32; i++) hm = fmaxf(hm, redM[i]);
            hmax  = hm;
            cur_b = b;
        }

        // ---- this warp's query
        const int q = chunk * 32 + wid;
        const float2 qv = ((const float2*)xb4)[q];
        const float hq = qv.y;
        const float zq = qv.x;
        const float aq = cs * hq;
        const float nm = -fabsf(aq) * hmax;

        const ull aq2 = pk2(aq, aq);
        const ull nm2 = pk2(nm, nm);
        const ull zq2 = pk2(zq, zq);

        ull s2a = 0, s2b = 0, w2a = 0, w2b = 0;

        // lane handles pairs lane + 32*k, k = 0..63 (128 keys)
        #pragma unroll 4
        for (int k = 0; k < 64; k += 2) {
            float4 va = kp[lane + 32 * k];
            float4 vb = kp[lane + 32 * (k + 1)];

            ull ha = pk2(va.x, va.y), na = pk2(va.z, va.w);
            ull hb = pk2(vb.x, vb.y), nb = pk2(vb.z, vb.w);

            ull la = fma2(nB22, add2(zq2, na) & ABSM, fma2(aq2, ha, nm2));
            ull lb = fma2(nB22, add2(zq2, nb) & ABSM, fma2(aq2, hb, nm2));

            float l0, l1; upk2(la, l0, l1);
            float l2, l3; upk2(lb, l2, l3);

            ull ea = pk2(ex2_fast(l0), ex2_fast(l1));
            ull eb = pk2(ex2_fast(l2), ex2_fast(l3));

            s2a = add2(s2a, ea);
            s2b = add2(s2b, eb);
            w2a = fma2(ea, ha, w2a);
            w2b = fma2(eb, hb, w2b);
        }

        float s0, s1, t0, t1; upk2(s2a, s0, s1); upk2(s2b, t0, t1);
        float u0, u1, v0, v1; upk2(w2a, u0, u1); upk2(w2b, v0, v1);
        float se = (s0 + s1) + (t0 + t1);
        float sw = (u0 + u1) + (v0 + v1);
        #pragma unroll
        for (int o = 16; o; o >>= 1) {
            se += __shfl_xor_sync(0xffffffffu, se, o);
            sw += __shfl_xor_sync(0xffffffffu, sw, o);
        }
        const float wv = sw / se;

        // ---- epilogue: this warp writes its query row (256 floats = 64 float4)
        float4* orow = (float4*)(out + ((size_t)b * S_LEN + q) * DMODEL);
        const float4* wv4 = (const float4*)sWv;
        float4 a0 = wv4[lane];
        a0.x *= wv; a0.y *= wv; a0.z *= wv; a0.w *= wv;
        orow[lane] = a0;
        float4 a1 = wv4[lane + 32];
        a1.x *= wv; a1.y *= wv; a1.z *= wv; a1.w *= wv;
        orow[lane + 32] = a1;
    }
}

extern "C" void kernel_launch(void* const* d_in, const int* in_sizes, int n_in,
                              void* d_out, int out_size)
{
    const float* x  = (const float*)d_in[0];
    const float* Wq = (const float*)d_in[1];
    const float* Wk = (const float*)d_in[2];
    const float* Wv = (const float*)d_in[3];
    float* out = (float*)d_out;

    dwsa_kernel<<<GRID, NTHREADS>>>(x, Wq, Wk, Wv, out);
}